// round 16
// baseline (speedup 1.0000x reference)
#include <cuda_runtime.h>
#include <math.h>

#define B_DIM 64
#define D_DIM 65536
#define S_SL  8
#define NTH   512
#define SLICE (D_DIM / S_SL)
#define QPT   (SLICE / 4 / NTH)      // 4 quads per thread
#define NBIG  1024                   // fine bins: 7 mantissa bits from x = 1.25
#define UBASE 16288                  // __float_as_uint(1.25f) >> 16
#define KB16  49056                  // key_of(1.25f) >> 16
#define FXS   262144.0f              // 2^18 fixed-point scale
#define CNT_SH 44
#define SUMMASK ((1ull << CNT_SH) - 1ull)
#define CAP_P 3072                   // positive-index list capacity (6KB u16)

// ---- __device__ scratch (allocation-free; BSS-zero; finisher re-zeroes) ----
__device__ unsigned long long g_hbin[B_DIM * NBIG];   // packed count<<44 | sum_fx
__device__ float g_sl_loc[B_DIM * S_SL];
__device__ float g_sl_bce[B_DIM * S_SL];
__device__ int   g_sl_pos[B_DIM * S_SL];
__device__ float g_row_loc[B_DIM];
__device__ float g_row_conf[B_DIM];
__device__ int   g_row_pos[B_DIM];
__device__ int   g_row_sel[B_DIM];
__device__ int   g_row_ctr[B_DIM];                    // self-resetting
__device__ int   g_ctr;                               // self-resetting

// accurate softplus (used once, for the threshold value)
__device__ __forceinline__ float softplus_f(float x) {
    return fmaxf(x, 0.0f) + log1pf(expf(-fabsf(x)));
}
// fast softplus for bulk summation (MUFU-based; abs err ~1e-6)
__device__ __forceinline__ float fast_sp(float x) {
    return fmaxf(x, 0.0f) + __logf(1.0f + __expf(-fabsf(x)));
}
__device__ __forceinline__ float sl1f(float d) {
    float ad = fabsf(d);
    return (ad < 1.0f) ? 0.5f * d * d : (ad - 0.5f);
}
__device__ __forceinline__ unsigned key_of(float x) {
    unsigned u = __float_as_uint(x);
    return (u & 0x80000000u) ? ~u : (u | 0x80000000u);
}
__device__ __forceinline__ float val_of_key(unsigned k) {
    unsigned u = (k & 0x80000000u) ? (k & 0x7FFFFFFFu) : ~k;
    return __uint_as_float(u);
}

template<int NWARP>
__device__ __forceinline__ float blk_sum(float v, float* red, int t) {
    #pragma unroll
    for (int o = 16; o > 0; o >>= 1) v += __shfl_down_sync(0xFFFFFFFFu, v, o);
    if ((t & 31) == 0) red[t >> 5] = v;
    __syncthreads();
    if (t < 32) {
        float w = (t < NWARP) ? red[t] : 0.0f;
        #pragma unroll
        for (int o = 16; o > 0; o >>= 1) w += __shfl_down_sync(0xFFFFFFFFu, w, o);
        if (t == 0) red[0] = w;
    }
    __syncthreads();
    float r = red[0];
    __syncthreads();
    return r;
}

// Warp-cooperative descending select over 256 shared bins (fallback only).
__device__ __forceinline__ int warp_select256(const unsigned* h, int k, int lane, int* rem_out) {
    int s = 0;
    #pragma unroll
    for (int m = 0; m < 8; m++) s += (int)h[255 - lane * 8 - m];
    int inc = s;
    #pragma unroll
    for (int o = 1; o < 32; o <<= 1) {
        int v = __shfl_up_sync(0xFFFFFFFFu, inc, o);
        if (lane >= o) inc += v;
    }
    int pre = inc - s;
    unsigned m = __ballot_sync(0xFFFFFFFFu, (pre < k) && (pre + s >= k));
    int chosen = __ffs(m) - 1;
    int bin = 0, rem = 0;
    if (lane == chosen) {
        int acc = pre, hi = 255 - lane * 8;
        #pragma unroll
        for (int b = 0; b < 8; b++) {
            int c = (int)h[hi - b];
            if (acc + c >= k) { bin = hi - b; rem = k - acc; break; }
            acc += c;
        }
    }
    bin = __shfl_sync(0xFFFFFFFFu, bin, chosen);
    rem = __shfl_sync(0xFFFFFFFFu, rem, chosen);
    *rem_out = rem;
    return bin;
}

// ================= ONE fused kernel: slice pass + per-row finisher =================
__global__ void __launch_bounds__(NTH) mbl_fused(
    const float4* __restrict__ loc_data,
    const float4* __restrict__ conf4,
    const float4* __restrict__ loc_t,
    const int4*   __restrict__ ct4,
    const float*  __restrict__ conf,
    const int*    __restrict__ ct,
    float* __restrict__ out)
{
    __shared__ float    red[32];
    __shared__ int      sc[NBIG];            // 4KB finisher bin counts
    __shared__ int      s2[16];
    __shared__ unsigned long long u64red[16];
    __shared__ unsigned rh[256];
    __shared__ unsigned short plist[CAP_P];  // 6KB positive slice-local indices
    __shared__ int      sh_np;
    __shared__ int      sh_fin, sh_last, sh_ib, sh_rem, sh_bin2, sh_rem2;
    __shared__ float    sred[24];

    const int t = threadIdx.x, lane = t & 31, w = t >> 5;
    const int row = blockIdx.x / S_SL, sl = blockIdx.x % S_SL;
    const int qr0 = row * (D_DIM / 4) + sl * (SLICE / 4);

    unsigned long long* hb = g_hbin + (size_t)row * NBIG;

    if (t == 0) sh_np = 0;
    __syncthreads();

    // ---------------- Pass-1 slice: stream conf/ct only; defer positives ----------------
    int npos = 0;
    #pragma unroll
    for (int j = 0; j < QPT; j++) {
        int qg = qr0 + t + j * NTH;
        float4 x = conf4[qg];
        int4   c = ct4[qg];
        float xs[4] = {x.x, x.y, x.z, x.w};
        int   cs[4] = {c.x, c.y, c.z, c.w};
        #pragma unroll
        for (int cc = 0; cc < 4; cc++) {
            if (cs[cc] > 0) {
                npos += 1;
                int p = atomicAdd(&sh_np, 1);
                if (p < CAP_P)
                    plist[p] = (unsigned short)(4 * (t + j * NTH) + cc);
            } else if (xs[cc] >= 1.25f) {       // ~10.6% of elements
                unsigned u = __float_as_uint(xs[cc]);
                int bin = min((int)(u >> 16) - UBASE, NBIG - 1);
                float sp = fast_sp(xs[cc]);
                unsigned long long pk = (1ull << CNT_SH)
                                      + (unsigned long long)(sp * FXS);
                atomicAdd(&hb[bin], pk);        // single RED.ADD.64
            }
        }
    }
    __syncthreads();

    // ---------------- Deferred positives: batched independent gathers ----------------
    float pb = 0.0f, ls = 0.0f;
    const int np_tot = sh_np;
    const size_t ebase = (size_t)row * D_DIM + (size_t)sl * SLICE;
    if (np_tot <= CAP_P) {
        for (int i = t; i < np_tot; i += NTH) {
            size_t e = ebase + plist[i];
            float xv = conf[e];                 // L1/L2-hot (just streamed)
            pb += fast_sp(-xv);
            float4 a = loc_data[e], b = loc_t[e];
            ls += sl1f(a.x - b.x) + sl1f(a.y - b.y) + sl1f(a.z - b.z) + sl1f(a.w - b.w);
        }
    } else {
        // overflow fallback: gated re-scan (L2-hot), statistically never taken
        #pragma unroll
        for (int j = 0; j < QPT; j++) {
            int qg = qr0 + t + j * NTH;
            float4 x = conf4[qg];
            int4   c = ct4[qg];
            float xs[4] = {x.x, x.y, x.z, x.w};
            int   cs[4] = {c.x, c.y, c.z, c.w};
            #pragma unroll
            for (int cc = 0; cc < 4; cc++) {
                if (cs[cc] > 0) {
                    size_t e = 4 * (size_t)qg + cc;
                    pb += fast_sp(-xs[cc]);
                    float4 a = loc_data[e], b = loc_t[e];
                    ls += sl1f(a.x - b.x) + sl1f(a.y - b.y)
                        + sl1f(a.z - b.z) + sl1f(a.w - b.w);
                }
            }
        }
    }

    float npos_r = blk_sum<16>((float)npos, red, t);
    float ls_r   = blk_sum<16>(ls,   red, t);
    float pb_r   = blk_sum<16>(pb,   red, t);
    if (t == 0) {
        g_sl_pos[blockIdx.x] = (int)npos_r;
        g_sl_loc[blockIdx.x] = ls_r;
        g_sl_bce[blockIdx.x] = pb_r;
        __threadfence();
        int v = atomicAdd(&g_row_ctr[row], 1);
        sh_fin = (v == S_SL - 1) ? 1 : 0;
        if (sh_fin) g_row_ctr[row] = 0;          // self-reset
    }
    __syncthreads();
    if (!sh_fin) return;
    __threadfence();   // acquire other slices' writes
    __syncthreads();

    // ---------------- Per-row finisher (this CTA only) ----------------
    if (t < 8) {
        sred[t]      = (float)g_sl_pos[row * S_SL + t];
        sred[t + 8]  = g_sl_bce[row * S_SL + t];
        sred[t + 16] = g_sl_loc[row * S_SL + t];
    }

    // load 2 bins per thread; decode counts; zero for next replay
    unsigned long long v0 = hb[2 * t], v1 = hb[2 * t + 1];
    int c0 = (int)(v0 >> CNT_SH), c1 = (int)(v1 >> CNT_SH);
    sc[2 * t] = c0; sc[2 * t + 1] = c1;
    hb[2 * t] = 0ull; hb[2 * t + 1] = 0ull;
    {
        int s = c0 + c1;
        #pragma unroll
        for (int o = 16; o > 0; o >>= 1) s += __shfl_down_sync(0xFFFFFFFFu, s, o);
        if (lane == 0) s2[w] = s;
    }
    __syncthreads();

    int npos_row, k;
    float pb_row, ls_row;
    {
        float np = 0.0f, pbs = 0.0f, lss = 0.0f;
        #pragma unroll
        for (int m = 0; m < 8; m++) { np += sred[m]; pbs += sred[m + 8]; lss += sred[m + 16]; }
        npos_row = (int)np; pb_row = pbs; ls_row = lss;
        k = min(3 * npos_row, D_DIM);
    }

    if (t == 0) {
        int tot = 0;
        #pragma unroll
        for (int m = 0; m < 16; m++) tot += s2[m];
        if (k > 0 && tot >= k) {
            // descending walk: warp segments (64 bins each) -> bins
            int acc = 0, seg = 15;
            for (int m = 15; m >= 0; m--) {
                if (acc + s2[m] >= k) { seg = m; break; }
                acc += s2[m];
            }
            int bin = seg * 64;
            for (int b = 63; b >= 0; b--) {
                int idx = seg * 64 + b;
                if (acc + sc[idx] >= k) { bin = idx; break; }
                acc += sc[idx];
            }
            sh_ib = bin; sh_rem = k - acc;
        } else sh_ib = -1;
    }
    __syncthreads();
    const int ib = sh_ib;
    const bool fast = (k > 0) && (ib >= 0) && (ib < NBIG - 1);

    // strict-part fixed-point sum over bins > ib (deterministic integer reduce)
    unsigned long long acc64 = 0ull;
    if (fast) {
        if (2 * t > ib)     acc64 += v0 & SUMMASK;
        if (2 * t + 1 > ib) acc64 += v1 & SUMMASK;
    }
    #pragma unroll
    for (int o = 16; o > 0; o >>= 1) acc64 += __shfl_down_sync(0xFFFFFFFFu, acc64, o);
    if (lane == 0) u64red[w] = acc64;
    __syncthreads();

    float csum = 0.0f;
    if (t == 0) {
        unsigned long long tt = 0ull;
        #pragma unroll
        for (int m = 0; m < 16; m++) tt += u64red[m];
        csum = (float)tt * (1.0f / FXS);
    }

    unsigned T = 0u; int req = 0;
    if (fast) {
        T = (unsigned)((KB16 + ib) << 16);       // boundary-bin lower-edge key
        req = sh_rem;
    } else if (k > 0) {
        // full fallback: exact 4-level radix over conf/ct (pathological rows only)
        csum = 0.0f;
        const size_t r0 = (size_t)row * D_DIM;
        unsigned prefix = 0u; int rem = k;
        for (int lvl = 0; lvl < 4; lvl++) {
            if (t < 256) rh[t] = 0;
            __syncthreads();
            for (int j = 0; j < D_DIM / NTH; j++) {
                size_t e = r0 + t + (size_t)j * NTH;
                if (ct[e] <= 0) {
                    unsigned kk = key_of(conf[e]);
                    if (lvl == 0 || (kk >> (32 - 8 * lvl)) == prefix)
                        atomicAdd(&rh[(kk >> (24 - 8 * lvl)) & 255u], 1u);
                }
            }
            __syncthreads();
            if (t < 32) { int r; int b = warp_select256(rh, rem, t, &r);
                          if (t == 0) { sh_bin2 = b; sh_rem2 = r; } }
            __syncthreads();
            prefix = (prefix << 8) | (unsigned)sh_bin2;
            rem = sh_rem2;
            __syncthreads();
        }
        T = prefix; req = rem;
        float fsum = 0.0f;
        for (int j = 0; j < D_DIM / NTH; j++) {
            size_t e = r0 + t + (size_t)j * NTH;
            if (ct[e] <= 0) {
                float xv = conf[e];
                if (key_of(xv) > T) fsum += softplus_f(xv);
            }
        }
        __syncthreads();
        csum += blk_sum<16>(fsum, red, t);       // only t==0's csum used below
    }
    __syncthreads();

    if (t == 0) {
        float tv = (req > 0) ? softplus_f(val_of_key(T)) : 0.0f;
        g_row_conf[row] = pb_row + csum + (float)req * tv;
        g_row_loc[row]  = ls_row;
        g_row_pos[row]  = npos_row;
        g_row_sel[row]  = npos_row + k;
        __threadfence();
        int v = atomicAdd(&g_ctr, 1);
        sh_last = (v == B_DIM - 1) ? 1 : 0;
        if (sh_last) g_ctr = 0;                  // self-reset
    }
    __syncthreads();
    if (!sh_last) return;
    __threadfence();
    __syncthreads();

    // ---------------- Global finisher: cross-row reduction ----------------
    if (t < 64) {
        float lc = g_row_loc[t], cf = g_row_conf[t];
        float ps = (float)g_row_pos[t], slv = (float)g_row_sel[t];
        #pragma unroll
        for (int o = 16; o > 0; o >>= 1) {
            lc  += __shfl_down_sync(0xFFFFFFFFu, lc,  o);
            cf  += __shfl_down_sync(0xFFFFFFFFu, cf,  o);
            ps  += __shfl_down_sync(0xFFFFFFFFu, ps,  o);
            slv += __shfl_down_sync(0xFFFFFFFFu, slv, o);
        }
        if ((t & 31) == 0) {
            red[(t >> 5) * 4 + 0] = lc; red[(t >> 5) * 4 + 1] = cf;
            red[(t >> 5) * 4 + 2] = ps; red[(t >> 5) * 4 + 3] = slv;
        }
    }
    __syncthreads();
    if (t == 0) {
        float lc = red[0] + red[4], cf = red[1] + red[5];
        float ps = red[2] + red[6], slv = red[3] + red[7];
        out[0] = lc / (4.0f * ps) / ps;
        out[1] = cf / slv / ps;
    }
}

extern "C" void kernel_launch(void* const* d_in, const int* in_sizes, int n_in,
                              void* d_out, int out_size)
{
    const float4* loc_data  = nullptr;
    const float4* loc_tgt   = nullptr;
    const float*  conf_data = nullptr;
    const int*    conf_tgt  = nullptr;
    for (int i = 0; i < n_in; i++) {
        if (in_sizes[i] == B_DIM * D_DIM * 4) {
            if (!loc_data) loc_data = (const float4*)d_in[i];
            else           loc_tgt  = (const float4*)d_in[i];
        } else {
            if (!conf_data) conf_data = (const float*)d_in[i];
            else            conf_tgt  = (const int*)d_in[i];
        }
    }

    mbl_fused<<<B_DIM * S_SL, NTH>>>(loc_data, (const float4*)conf_data,
                                     loc_tgt, (const int4*)conf_tgt,
                                     conf_data, conf_tgt, (float*)d_out);
}

// round 17
// speedup vs baseline: 1.2976x; 1.2976x over previous
#include <cuda_runtime.h>
#include <math.h>

#define B_DIM 64
#define D_DIM 65536
#define S_SL  8
#define NTH   512
#define SLICE (D_DIM / S_SL)
#define QPT   (SLICE / 4 / NTH)      // 4 quads per thread
#define NBIG  1024                   // fine bins: 7 mantissa bits from x = 1.25
#define UBASE 16288                  // __float_as_uint(1.25f) >> 16
#define KB16  49056                  // key_of(1.25f) >> 16
#define FXS   262144.0f              // 2^18 fixed-point scale
#define CNT_SH 44
#define SUMMASK ((1ull << CNT_SH) - 1ull)

// ---- __device__ scratch (allocation-free; BSS-zero; finisher re-zeroes) ----
__device__ unsigned long long g_hbin[B_DIM * NBIG];   // packed count<<44 | sum_fx
__device__ float g_sl_loc[B_DIM * S_SL];
__device__ float g_sl_bce[B_DIM * S_SL];
__device__ int   g_sl_pos[B_DIM * S_SL];
__device__ float g_row_loc[B_DIM];
__device__ float g_row_conf[B_DIM];
__device__ int   g_row_pos[B_DIM];
__device__ int   g_row_sel[B_DIM];
__device__ int   g_row_ctr[B_DIM];                    // self-resetting
__device__ int   g_ctr;                               // self-resetting

// accurate softplus (used once, for the threshold value)
__device__ __forceinline__ float softplus_f(float x) {
    return fmaxf(x, 0.0f) + log1pf(expf(-fabsf(x)));
}
// fast softplus for bulk summation (MUFU-based; abs err ~1e-6)
__device__ __forceinline__ float fast_sp(float x) {
    return fmaxf(x, 0.0f) + __logf(1.0f + __expf(-fabsf(x)));
}
__device__ __forceinline__ float sl1f(float d) {
    float ad = fabsf(d);
    return (ad < 1.0f) ? 0.5f * d * d : (ad - 0.5f);
}
__device__ __forceinline__ unsigned key_of(float x) {
    unsigned u = __float_as_uint(x);
    return (u & 0x80000000u) ? ~u : (u | 0x80000000u);
}
__device__ __forceinline__ float val_of_key(unsigned k) {
    unsigned u = (k & 0x80000000u) ? (k & 0x7FFFFFFFu) : ~k;
    return __uint_as_float(u);
}

template<int NWARP>
__device__ __forceinline__ float blk_sum(float v, float* red, int t) {
    #pragma unroll
    for (int o = 16; o > 0; o >>= 1) v += __shfl_down_sync(0xFFFFFFFFu, v, o);
    if ((t & 31) == 0) red[t >> 5] = v;
    __syncthreads();
    if (t < 32) {
        float w = (t < NWARP) ? red[t] : 0.0f;
        #pragma unroll
        for (int o = 16; o > 0; o >>= 1) w += __shfl_down_sync(0xFFFFFFFFu, w, o);
        if (t == 0) red[0] = w;
    }
    __syncthreads();
    float r = red[0];
    __syncthreads();
    return r;
}

// Warp-cooperative descending select over 256 shared bins (fallback only).
__device__ __forceinline__ int warp_select256(const unsigned* h, int k, int lane, int* rem_out) {
    int s = 0;
    #pragma unroll
    for (int m = 0; m < 8; m++) s += (int)h[255 - lane * 8 - m];
    int inc = s;
    #pragma unroll
    for (int o = 1; o < 32; o <<= 1) {
        int v = __shfl_up_sync(0xFFFFFFFFu, inc, o);
        if (lane >= o) inc += v;
    }
    int pre = inc - s;
    unsigned m = __ballot_sync(0xFFFFFFFFu, (pre < k) && (pre + s >= k));
    int chosen = __ffs(m) - 1;
    int bin = 0, rem = 0;
    if (lane == chosen) {
        int acc = pre, hi = 255 - lane * 8;
        #pragma unroll
        for (int b = 0; b < 8; b++) {
            int c = (int)h[hi - b];
            if (acc + c >= k) { bin = hi - b; rem = k - acc; break; }
            acc += c;
        }
    }
    bin = __shfl_sync(0xFFFFFFFFu, bin, chosen);
    rem = __shfl_sync(0xFFFFFFFFu, rem, chosen);
    *rem_out = rem;
    return bin;
}

// ================= ONE fused kernel: slice pass + per-row finisher =================
__global__ void __launch_bounds__(NTH) mbl_fused(
    const float4* __restrict__ loc_data,
    const float4* __restrict__ conf4,
    const float4* __restrict__ loc_t,
    const int4*   __restrict__ ct4,
    const float*  __restrict__ conf,
    const int*    __restrict__ ct,
    float* __restrict__ out)
{
    __shared__ float    red[48];
    __shared__ int      sc[NBIG];            // 4KB finisher bin counts
    __shared__ int      s2[16];
    __shared__ unsigned long long u64red[16];
    __shared__ unsigned rh[256];
    __shared__ int      sh_fin, sh_last, sh_ib, sh_rem, sh_bin2, sh_rem2;
    __shared__ float    sred[24];

    const int t = threadIdx.x, lane = t & 31, w = t >> 5;
    const int row = blockIdx.x / S_SL, sl = blockIdx.x % S_SL;
    const int qr0 = row * (D_DIM / 4) + sl * (SLICE / 4);

    unsigned long long* hb = g_hbin + (size_t)row * NBIG;

    // ---------------- Pass-1 slice (champion loop; streaming loads) ----------------
    int   npos = 0;
    float pb = 0.0f, ls = 0.0f;
    #pragma unroll
    for (int j = 0; j < QPT; j++) {
        int qg = qr0 + t + j * NTH;
        float4 x = __ldcs(&conf4[qg]);      // evict-first: single-use stream
        int4   c = __ldcs(&ct4[qg]);
        float xs[4] = {x.x, x.y, x.z, x.w};
        int   cs[4] = {c.x, c.y, c.z, c.w};
        #pragma unroll
        for (int cc = 0; cc < 4; cc++) {
            if (cs[cc] > 0) {
                size_t e = 4 * (size_t)qg + cc;
                npos += 1; pb += fast_sp(-xs[cc]);
                float4 a = loc_data[e], b = loc_t[e];
                ls += sl1f(a.x - b.x) + sl1f(a.y - b.y) + sl1f(a.z - b.z) + sl1f(a.w - b.w);
            } else if (xs[cc] >= 1.25f) {       // ~10.6% of elements
                unsigned u = __float_as_uint(xs[cc]);
                int bin = min((int)(u >> 16) - UBASE, NBIG - 1);
                float sp = fast_sp(xs[cc]);
                unsigned long long pk = (1ull << CNT_SH)
                                      + (unsigned long long)(sp * FXS);
                atomicAdd(&hb[bin], pk);        // single RED.ADD.64
            }
        }
    }

    // ---- fused 3-way block reduction (one barrier pair instead of six) ----
    {
        float a = (float)npos, b = pb, c2 = ls;
        #pragma unroll
        for (int o = 16; o > 0; o >>= 1) {
            a  += __shfl_down_sync(0xFFFFFFFFu, a,  o);
            b  += __shfl_down_sync(0xFFFFFFFFu, b,  o);
            c2 += __shfl_down_sync(0xFFFFFFFFu, c2, o);
        }
        if (lane == 0) { red[w] = a; red[w + 16] = b; red[w + 32] = c2; }
    }
    __syncthreads();
    if (t < 16) {
        float a = red[t], b = red[t + 16], c2 = red[t + 32];
        #pragma unroll
        for (int o = 8; o > 0; o >>= 1) {
            a  += __shfl_down_sync(0xFFFFu, a,  o);
            b  += __shfl_down_sync(0xFFFFu, b,  o);
            c2 += __shfl_down_sync(0xFFFFu, c2, o);
        }
        if (t == 0) {
            g_sl_pos[blockIdx.x] = (int)a;
            g_sl_bce[blockIdx.x] = b;
            g_sl_loc[blockIdx.x] = c2;
            __threadfence();
            int v = atomicAdd(&g_row_ctr[row], 1);
            sh_fin = (v == S_SL - 1) ? 1 : 0;
            if (sh_fin) g_row_ctr[row] = 0;      // self-reset
        }
    }
    __syncthreads();
    if (!sh_fin) return;
    __threadfence();   // acquire other slices' writes
    __syncthreads();

    // ---------------- Per-row finisher (this CTA only) ----------------
    if (t < 8) {
        sred[t]      = (float)g_sl_pos[row * S_SL + t];
        sred[t + 8]  = g_sl_bce[row * S_SL + t];
        sred[t + 16] = g_sl_loc[row * S_SL + t];
    }

    // load 2 bins per thread; decode counts; zero for next replay
    unsigned long long v0 = hb[2 * t], v1 = hb[2 * t + 1];
    int c0 = (int)(v0 >> CNT_SH), c1 = (int)(v1 >> CNT_SH);
    sc[2 * t] = c0; sc[2 * t + 1] = c1;
    hb[2 * t] = 0ull; hb[2 * t + 1] = 0ull;
    {
        int s = c0 + c1;
        #pragma unroll
        for (int o = 16; o > 0; o >>= 1) s += __shfl_down_sync(0xFFFFFFFFu, s, o);
        if (lane == 0) s2[w] = s;
    }
    __syncthreads();

    int npos_row, k;
    float pb_row, ls_row;
    {
        float np = 0.0f, pbs = 0.0f, lss = 0.0f;
        #pragma unroll
        for (int m = 0; m < 8; m++) { np += sred[m]; pbs += sred[m + 8]; lss += sred[m + 16]; }
        npos_row = (int)np; pb_row = pbs; ls_row = lss;
        k = min(3 * npos_row, D_DIM);
    }

    if (t == 0) {
        int tot = 0;
        #pragma unroll
        for (int m = 0; m < 16; m++) tot += s2[m];
        if (k > 0 && tot >= k) {
            // descending walk: warp segments (64 bins each) -> bins
            int acc = 0, seg = 15;
            for (int m = 15; m >= 0; m--) {
                if (acc + s2[m] >= k) { seg = m; break; }
                acc += s2[m];
            }
            int bin = seg * 64;
            for (int b = 63; b >= 0; b--) {
                int idx = seg * 64 + b;
                if (acc + sc[idx] >= k) { bin = idx; break; }
                acc += sc[idx];
            }
            sh_ib = bin; sh_rem = k - acc;
        } else sh_ib = -1;
    }
    __syncthreads();
    const int ib = sh_ib;
    const bool fast = (k > 0) && (ib >= 0) && (ib < NBIG - 1);

    // strict-part fixed-point sum over bins > ib (deterministic integer reduce)
    unsigned long long acc64 = 0ull;
    if (fast) {
        if (2 * t > ib)     acc64 += v0 & SUMMASK;
        if (2 * t + 1 > ib) acc64 += v1 & SUMMASK;
    }
    #pragma unroll
    for (int o = 16; o > 0; o >>= 1) acc64 += __shfl_down_sync(0xFFFFFFFFu, acc64, o);
    if (lane == 0) u64red[w] = acc64;
    __syncthreads();

    float csum = 0.0f;
    if (t == 0) {
        unsigned long long tt = 0ull;
        #pragma unroll
        for (int m = 0; m < 16; m++) tt += u64red[m];
        csum = (float)tt * (1.0f / FXS);
    }

    unsigned T = 0u; int req = 0;
    if (fast) {
        T = (unsigned)((KB16 + ib) << 16);       // boundary-bin lower-edge key
        req = sh_rem;
    } else if (k > 0) {
        // full fallback: exact 4-level radix over conf/ct (pathological rows only)
        csum = 0.0f;
        const size_t r0 = (size_t)row * D_DIM;
        unsigned prefix = 0u; int rem = k;
        for (int lvl = 0; lvl < 4; lvl++) {
            if (t < 256) rh[t] = 0;
            __syncthreads();
            for (int j = 0; j < D_DIM / NTH; j++) {
                size_t e = r0 + t + (size_t)j * NTH;
                if (ct[e] <= 0) {
                    unsigned kk = key_of(conf[e]);
                    if (lvl == 0 || (kk >> (32 - 8 * lvl)) == prefix)
                        atomicAdd(&rh[(kk >> (24 - 8 * lvl)) & 255u], 1u);
                }
            }
            __syncthreads();
            if (t < 32) { int r; int b = warp_select256(rh, rem, t, &r);
                          if (t == 0) { sh_bin2 = b; sh_rem2 = r; } }
            __syncthreads();
            prefix = (prefix << 8) | (unsigned)sh_bin2;
            rem = sh_rem2;
            __syncthreads();
        }
        T = prefix; req = rem;
        float fsum = 0.0f;
        for (int j = 0; j < D_DIM / NTH; j++) {
            size_t e = r0 + t + (size_t)j * NTH;
            if (ct[e] <= 0) {
                float xv = conf[e];
                if (key_of(xv) > T) fsum += softplus_f(xv);
            }
        }
        __syncthreads();
        csum += blk_sum<16>(fsum, red, t);       // only t==0's csum used below
    }
    __syncthreads();

    if (t == 0) {
        float tv = (req > 0) ? softplus_f(val_of_key(T)) : 0.0f;
        g_row_conf[row] = pb_row + csum + (float)req * tv;
        g_row_loc[row]  = ls_row;
        g_row_pos[row]  = npos_row;
        g_row_sel[row]  = npos_row + k;
        __threadfence();
        int v = atomicAdd(&g_ctr, 1);
        sh_last = (v == B_DIM - 1) ? 1 : 0;
        if (sh_last) g_ctr = 0;                  // self-reset
    }
    __syncthreads();
    if (!sh_last) return;
    __threadfence();
    __syncthreads();

    // ---------------- Global finisher: cross-row reduction ----------------
    if (t < 64) {
        float lc = g_row_loc[t], cf = g_row_conf[t];
        float ps = (float)g_row_pos[t], slv = (float)g_row_sel[t];
        #pragma unroll
        for (int o = 16; o > 0; o >>= 1) {
            lc  += __shfl_down_sync(0xFFFFFFFFu, lc,  o);
            cf  += __shfl_down_sync(0xFFFFFFFFu, cf,  o);
            ps  += __shfl_down_sync(0xFFFFFFFFu, ps,  o);
            slv += __shfl_down_sync(0xFFFFFFFFu, slv, o);
        }
        if ((t & 31) == 0) {
            red[(t >> 5) * 4 + 0] = lc; red[(t >> 5) * 4 + 1] = cf;
            red[(t >> 5) * 4 + 2] = ps; red[(t >> 5) * 4 + 3] = slv;
        }
    }
    __syncthreads();
    if (t == 0) {
        float lc = red[0] + red[4], cf = red[1] + red[5];
        float ps = red[2] + red[6], slv = red[3] + red[7];
        out[0] = lc / (4.0f * ps) / ps;
        out[1] = cf / slv / ps;
    }
}

extern "C" void kernel_launch(void* const* d_in, const int* in_sizes, int n_in,
                              void* d_out, int out_size)
{
    const float4* loc_data  = nullptr;
    const float4* loc_tgt   = nullptr;
    const float*  conf_data = nullptr;
    const int*    conf_tgt  = nullptr;
    for (int i = 0; i < n_in; i++) {
        if (in_sizes[i] == B_DIM * D_DIM * 4) {
            if (!loc_data) loc_data = (const float4*)d_in[i];
            else           loc_tgt  = (const float4*)d_in[i];
        } else {
            if (!conf_data) conf_data = (const float*)d_in[i];
            else            conf_tgt  = (const int*)d_in[i];
        }
    }

    mbl_fused<<<B_DIM * S_SL, NTH>>>(loc_data, (const float4*)conf_data,
                                     loc_tgt, (const int4*)conf_tgt,
                                     conf_data, conf_tgt, (float*)d_out);
}